// round 4
// baseline (speedup 1.0000x reference)
#include <cuda_runtime.h>

#define EPSV 1e-4f
#define T_LEN 4096
#define DH 1024
#define C3 3072
#define TT 128          // timesteps per tile (4 per lane)
#define NTILE 32        // 4096 / 128
#define PITCH 132       // smem row pitch in floats: 16B-aligned, conflict-free

__device__ __forceinline__ float sigmoid_f(float x) {
    // exact-ish: MUFU.EX2 + MUFU.RCP — used on the compounding (forget-gate) path
    return __fdividef(1.0f, 1.0f + __expf(-x));
}

__device__ __forceinline__ float tanh_fast(float x) {
    // HW MUFU.TANH (sm_75+): 1 MUFU op. Used only on non-compounding paths.
    float y;
    asm("tanh.approx.f32 %0, %1;" : "=f"(y) : "f"(x));
    return y;
}

// Block: 256 threads = 8 warps, owns (batch b, channels d0..d0+7).
// Tile = 128 timesteps. Warp w computes channel d0+w; lane l owns timesteps
// 4l..4l+3 (sequential in-lane, warp-scan across lanes, carry across tiles).
// Loads/stores are float4, transposed through padded smem.
// Output store of tile k is deferred to iteration k+1 so the loop needs only
// 2 barriers per tile.
__global__ __launch_bounds__(256) void glru_scan_kernel(
    const float* __restrict__ x, float* __restrict__ out)
{
    const int b   = blockIdx.y;
    const int d0  = blockIdx.x * 8;
    const int tid = threadIdx.x;
    const int w   = tid >> 5;        // channel within group (compute mapping)
    const int l   = tid & 31;        // lane = 4-timestep segment
    const int tl  = tid >> 1;        // time row 0..127 (load mapping)
    const int cq  = (tid & 1) * 4;   // channel quad 0 or 4 (load mapping)

    __shared__ float s_in[3][8][PITCH];
    __shared__ float s_out[8][PITCH];

    const float* pin = x + ((size_t)(b * T_LEN) + tl) * C3 + d0 + cq;
    float*      pout = out + ((size_t)(b * T_LEN) + tl) * DH + d0 + cq;

    // Prefetch tile 0
    float4 r0 = *(const float4*)(pin);
    float4 r1 = *(const float4*)(pin + DH);
    float4 r2 = *(const float4*)(pin + 2 * DH);
    pin += (size_t)TT * C3;

    float a_carry = 1.0f;   // running cumprod carry
    float s_carry = 0.0f;   // running cumsum carry

    for (int k = 0; k < NTILE; ++k) {
        __syncthreads();   // prev tile's s_in reads done AND its s_out writes visible

        // Read back previous tile's output (deferred store)
        float4 ov;
        if (k > 0) {
            ov.x = s_out[cq + 0][tl];
            ov.y = s_out[cq + 1][tl];
            ov.z = s_out[cq + 2][tl];
            ov.w = s_out[cq + 3][tl];
        }

        // Stage current tile's inputs (already in registers)
        s_in[0][cq + 0][tl] = r0.x;  s_in[0][cq + 1][tl] = r0.y;
        s_in[0][cq + 2][tl] = r0.z;  s_in[0][cq + 3][tl] = r0.w;
        s_in[1][cq + 0][tl] = r1.x;  s_in[1][cq + 1][tl] = r1.y;
        s_in[1][cq + 2][tl] = r1.z;  s_in[1][cq + 3][tl] = r1.w;
        s_in[2][cq + 0][tl] = r2.x;  s_in[2][cq + 1][tl] = r2.y;
        s_in[2][cq + 2][tl] = r2.z;  s_in[2][cq + 3][tl] = r2.w;

        // Prefetch next tile (overlaps compute below)
        if (k + 1 < NTILE) {
            r0 = *(const float4*)(pin);
            r1 = *(const float4*)(pin + DH);
            r2 = *(const float4*)(pin + 2 * DH);
            pin += (size_t)TT * C3;
        }

        // Deferred coalesced store of previous tile's output
        if (k > 0) {
            *(float4*)pout = ov;
            pout += (size_t)TT * DH;
        }

        __syncthreads();   // s_in ready

        const float4 xi = *(const float4*)&s_in[0][w][4 * l];
        const float4 xg = *(const float4*)&s_in[1][w][4 * l];
        const float4 xo = *(const float4*)&s_in[2][w][4 * l];

        float fg[4], kv[4], og[4];
        {
            const float vxi[4] = {xi.x, xi.y, xi.z, xi.w};
            const float vxg[4] = {xg.x, xg.y, xg.z, xg.w};
            const float vxo[4] = {xo.x, xo.y, xo.z, xo.w};
            #pragma unroll
            for (int j = 0; j < 4; ++j) {
                float ig = sigmoid_f(vxg[j]);      // exact: compounding path
                fg[j] = 1.0f - ig;
                kv[j] = tanh_fast(vxi[j]) * ig;    // approx: averaged in cumsum
                og[j] = sigmoid_f(vxo[j]);         // exact: direct output factor
            }
        }

        // Lane-local inclusive cumprod of forget gates
        float pc[4];
        pc[0] = fg[0];
        pc[1] = pc[0] * fg[1];
        pc[2] = pc[1] * fg[2];
        pc[3] = pc[2] * fg[3];

        // Warp inclusive scan (product) of lane totals
        float incP = pc[3];
        #pragma unroll
        for (int off = 1; off < 32; off <<= 1) {
            float v = __shfl_up_sync(0xffffffffu, incP, off);
            if (l >= off) incP *= v;
        }
        float exP = __shfl_up_sync(0xffffffffu, incP, 1);
        if (l == 0) exP = 1.0f;
        const float abase = a_carry * exP;

        float a[4], term[4];
        #pragma unroll
        for (int j = 0; j < 4; ++j) {
            a[j]    = abase * pc[j];
            term[j] = __fdividef(kv[j], a[j] + EPSV);
        }

        // Lane-local inclusive cumsum of terms
        float sc[4];
        sc[0] = term[0];
        sc[1] = sc[0] + term[1];
        sc[2] = sc[1] + term[2];
        sc[3] = sc[2] + term[3];

        // Warp inclusive scan (sum) of lane totals
        float incS = sc[3];
        #pragma unroll
        for (int off = 1; off < 32; off <<= 1) {
            float v = __shfl_up_sync(0xffffffffu, incS, off);
            if (l >= off) incS += v;
        }
        float exS = __shfl_up_sync(0xffffffffu, incS, 1);
        if (l == 0) exS = 0.0f;
        const float sbase = s_carry + exS;

        float4 o;
        o.x = tanh_fast(a[0] * (sbase + sc[0])) * og[0];
        o.y = tanh_fast(a[1] * (sbase + sc[1])) * og[1];
        o.z = tanh_fast(a[2] * (sbase + sc[2])) * og[2];
        o.w = tanh_fast(a[3] * (sbase + sc[3])) * og[3];

        // Carry update from lane 31's inclusive totals
        a_carry *= __shfl_sync(0xffffffffu, incP, 31);
        s_carry += __shfl_sync(0xffffffffu, incS, 31);

        // Stage output for next iteration's coalesced store
        *(float4*)&s_out[w][4 * l] = o;
    }

    // Epilogue: flush last tile's output
    __syncthreads();
    float4 ov;
    ov.x = s_out[cq + 0][tl];
    ov.y = s_out[cq + 1][tl];
    ov.z = s_out[cq + 2][tl];
    ov.w = s_out[cq + 3][tl];
    *(float4*)pout = ov;
}

extern "C" void kernel_launch(void* const* d_in, const int* in_sizes, int n_in,
                              void* d_out, int out_size)
{
    const float* x = (const float*)d_in[0];
    float* out = (float*)d_out;
    dim3 grid(DH / 8, 8);   // 128 channel-groups x 8 batches = 1024 blocks
    glru_scan_kernel<<<grid, 256>>>(x, out);
}

// round 5
// speedup vs baseline: 1.0436x; 1.0436x over previous
#include <cuda_runtime.h>

#define EPSV 1e-4f
#define T_LEN 4096
#define DH 1024
#define C3 3072
#define TT 128          // timesteps per tile (4 per lane)
#define NTILE 32        // 4096 / 128
#define PITCH 132       // smem row pitch in floats: 16B-aligned, conflict-free

__device__ __forceinline__ float sigmoid_f(float x) {
    // MUFU.EX2 + MUFU.RCP — exact enough for the compounding cumprod path
    return __fdividef(1.0f, 1.0f + __expf(-x));
}

__device__ __forceinline__ float tanh_fast(float x) {
    // HW MUFU.TANH (sm_75+): 1 MUFU op. Non-compounding paths only.
    float y;
    asm("tanh.approx.f32 %0, %1;" : "=f"(y) : "f"(x));
    return y;
}

// Block: 256 threads = 8 warps, owns (batch b, channels d0..d0+7).
// Tile = 128 timesteps. Warp w computes channel d0+w; lane l owns timesteps
// 4l..4l+3 (sequential in-lane, warp-scan across lanes, carry across tiles).
//
// L1-wavefront diet:
//  - Activations fg/kv are computed on the LOAD side (from registers) and only
//    those 2 columns are staged through smem (was 3 raw columns).
//  - The output gate og = sigmoid(xo) never transposes: it's computed load-side,
//    held one iteration in registers, and applied at the deferred readback/store
//    (store mapping == load mapping).
//  - Output store of tile k is deferred to iteration k+1 -> 2 barriers/tile.
__global__ __launch_bounds__(256) void glru_scan_kernel(
    const float* __restrict__ x, float* __restrict__ out)
{
    const int b   = blockIdx.y;
    const int d0  = blockIdx.x * 8;
    const int tid = threadIdx.x;
    const int w   = tid >> 5;        // channel within group (compute mapping)
    const int l   = tid & 31;        // lane = 4-timestep segment
    const int tl  = tid >> 1;        // time row 0..127 (load/store mapping)
    const int cq  = (tid & 1) * 4;   // channel quad 0 or 4 (load/store mapping)

    __shared__ float s_in[2][8][PITCH];   // [0]=fg, [1]=kv   ([ch][t], padded)
    __shared__ float s_out[8][PITCH];     // tanh(y) (og applied at store)

    const float* pin = x + ((size_t)(b * T_LEN) + tl) * C3 + d0 + cq;
    float*      pout = out + ((size_t)(b * T_LEN) + tl) * DH + d0 + cq;

    // Prefetch tile 0
    float4 r0 = *(const float4*)(pin);            // xi
    float4 r1 = *(const float4*)(pin + DH);       // xg
    float4 r2 = *(const float4*)(pin + 2 * DH);   // xo
    pin += (size_t)TT * C3;

    float4 og_prev;          // og of tile k-1 (store side), valid from k=1
    float a_carry = 1.0f;    // running cumprod carry
    float s_carry = 0.0f;    // running cumsum carry

    for (int k = 0; k < NTILE; ++k) {
        __syncthreads();   // prev s_in consumed AND prev s_out visible

        // Deferred output of tile k-1: readback tanh(y), apply held og
        float4 ov;
        if (k > 0) {
            ov.x = s_out[cq + 0][tl] * og_prev.x;
            ov.y = s_out[cq + 1][tl] * og_prev.y;
            ov.z = s_out[cq + 2][tl] * og_prev.z;
            ov.w = s_out[cq + 3][tl] * og_prev.w;
        }

        // Load-side activation compute + staging of tile k (fg, kv only)
        {
            const float vxi[4] = {r0.x, r0.y, r0.z, r0.w};
            const float vxg[4] = {r1.x, r1.y, r1.z, r1.w};
            #pragma unroll
            for (int j = 0; j < 4; ++j) {
                float ig = sigmoid_f(vxg[j]);
                s_in[0][cq + j][tl] = 1.0f - ig;            // fg
                s_in[1][cq + j][tl] = tanh_fast(vxi[j]) * ig; // kv
            }
        }
        // og for tile k, held in registers until iteration k+1's store
        og_prev.x = sigmoid_f(r2.x);
        og_prev.y = sigmoid_f(r2.y);
        og_prev.z = sigmoid_f(r2.z);
        og_prev.w = sigmoid_f(r2.w);

        // Prefetch tile k+1 (overlaps compute below)
        if (k + 1 < NTILE) {
            r0 = *(const float4*)(pin);
            r1 = *(const float4*)(pin + DH);
            r2 = *(const float4*)(pin + 2 * DH);
            pin += (size_t)TT * C3;
        }

        // Deferred coalesced store of tile k-1
        if (k > 0) {
            *(float4*)pout = ov;
            pout += (size_t)TT * DH;
        }

        __syncthreads();   // s_in ready

        const float4 f4 = *(const float4*)&s_in[0][w][4 * l];
        const float4 v4 = *(const float4*)&s_in[1][w][4 * l];
        const float kv[4] = {v4.x, v4.y, v4.z, v4.w};

        // Lane-local inclusive cumprod of forget gates
        float pc[4];
        pc[0] = f4.x;
        pc[1] = pc[0] * f4.y;
        pc[2] = pc[1] * f4.z;
        pc[3] = pc[2] * f4.w;

        // Warp inclusive scan (product) of lane totals
        float incP = pc[3];
        #pragma unroll
        for (int off = 1; off < 32; off <<= 1) {
            float v = __shfl_up_sync(0xffffffffu, incP, off);
            if (l >= off) incP *= v;
        }
        float exP = __shfl_up_sync(0xffffffffu, incP, 1);
        if (l == 0) exP = 1.0f;
        const float abase = a_carry * exP;

        // term_j = kv_j / (a_j + eps), lane-local inclusive cumsum
        float sc[4];
        sc[0] = __fdividef(kv[0], abase * pc[0] + EPSV);
        sc[1] = sc[0] + __fdividef(kv[1], abase * pc[1] + EPSV);
        sc[2] = sc[1] + __fdividef(kv[2], abase * pc[2] + EPSV);
        sc[3] = sc[2] + __fdividef(kv[3], abase * pc[3] + EPSV);

        // Warp inclusive scan (sum) of lane totals
        float incS = sc[3];
        #pragma unroll
        for (int off = 1; off < 32; off <<= 1) {
            float v = __shfl_up_sync(0xffffffffu, incS, off);
            if (l >= off) incS += v;
        }
        float exS = __shfl_up_sync(0xffffffffu, incS, 1);
        if (l == 0) exS = 0.0f;
        const float sbase = s_carry + exS;

        // Stage tanh(y); og multiplied at store time
        float4 o;
        o.x = tanh_fast(abase * pc[0] * (sbase + sc[0]));
        o.y = tanh_fast(abase * pc[1] * (sbase + sc[1]));
        o.z = tanh_fast(abase * pc[2] * (sbase + sc[2]));
        o.w = tanh_fast(abase * pc[3] * (sbase + sc[3]));
        *(float4*)&s_out[w][4 * l] = o;

        // Carry update from lane 31's inclusive totals
        a_carry *= __shfl_sync(0xffffffffu, incP, 31);
        s_carry += __shfl_sync(0xffffffffu, incS, 31);
    }

    // Epilogue: flush last tile's output
    __syncthreads();
    float4 ov;
    ov.x = s_out[cq + 0][tl] * og_prev.x;
    ov.y = s_out[cq + 1][tl] * og_prev.y;
    ov.z = s_out[cq + 2][tl] * og_prev.z;
    ov.w = s_out[cq + 3][tl] * og_prev.w;
    *(float4*)pout = ov;
}

extern "C" void kernel_launch(void* const* d_in, const int* in_sizes, int n_in,
                              void* d_out, int out_size)
{
    const float* x = (const float*)d_in[0];
    float* out = (float*)d_out;
    dim3 grid(DH / 8, 8);   // 128 channel-groups x 8 batches = 1024 blocks
    glru_scan_kernel<<<grid, 256>>>(x, out);
}